// round 10
// baseline (speedup 1.0000x reference)
#include <cuda_runtime.h>
#include <cuda_bf16.h>
#include <cuda_fp8.h>
#include <cfloat>
#include <cstdint>

#define D        512
#define KCB      1024
#define NROWS    65536
#define MARGIN   20.0f
#define CAP      65536
#define MAXCAND  16
#define TIEBREAK 2e-3f

#define BM       128            // rows per CTA
#define BN       256            // codewords per phase
#define NPH      4              // 1024 / 256
#define KC       256            // fp8 K elems per stage (256 B/row)
#define NSTG     (NPH * (D / KC))   // 8
#define NTH      512

// smem layout (bytes)
#define SM_C2    0               // float[1024]
#define SM_BUF   4096
#define STRIDE_B 272             // 256B data + 16B pad -> conflict-free ldmatrix
#define A_BYTES  (BM * STRIDE_B)          // 34816
#define B_BYTES  (BN * STRIDE_B)          // 69632
#define BUF_BYTES (A_BYTES + B_BYTES)     // 104448
#define SM_TOTAL (SM_BUF + 2 * BUF_BYTES) // 212992

// ---- device scratch (no cudaMalloc allowed) ----
__device__ uint8_t g_xq[(size_t)NROWS * D];          // 32 MB e4m3
__device__ uint8_t g_cbq[KCB * D];                   // 0.5 MB e4m3
__device__ float g_d2[(size_t)NROWS * KCB];          // 256 MB approx distances
__device__ float g_c2[KCB];
__device__ int   g_flag_rows[CAP];
__device__ int   g_flag_count;

// ================= PTX helpers (baseline sm_80/sm_89 features) =================
__device__ __forceinline__ uint32_t smem_u32(const void* p) {
    uint32_t a;
    asm("{ .reg .u64 t; cvta.to.shared.u64 t, %1; cvt.u32.u64 %0, t; }" : "=r"(a) : "l"(p));
    return a;
}
#define CP16(s, g)   asm volatile("cp.async.ca.shared.global [%0], [%1], 16;" :: "r"(s), "l"(g))
#define CPCOMMIT()   asm volatile("cp.async.commit_group;")
#define CPWAIT0()    asm volatile("cp.async.wait_group 0;")
#define LDSM4(r0, r1, r2, r3, a) \
    asm volatile("ldmatrix.sync.aligned.m8n8.x4.shared.b16 {%0,%1,%2,%3}, [%4];" \
                 : "=r"(r0), "=r"(r1), "=r"(r2), "=r"(r3) : "r"(a))

// fp8 e4m3 MMA, K=32. Fragment layout == bf16 k16 with 2 fp8 per 16-bit lane.
__device__ __forceinline__ void mma_fp8(float* c, const uint32_t* a, uint32_t b0, uint32_t b1) {
    asm volatile(
        "mma.sync.aligned.m16n8k32.row.col.f32.e4m3.e4m3.f32 "
        "{%0,%1,%2,%3}, {%4,%5,%6,%7}, {%8,%9}, {%0,%1,%2,%3};"
        : "+f"(c[0]), "+f"(c[1]), "+f"(c[2]), "+f"(c[3])
        : "r"(a[0]), "r"(a[1]), "r"(a[2]), "r"(a[3]), "r"(b0), "r"(b1));
}

__device__ __forceinline__ uint32_t pack_fp8x4(float4 v) {
    __nv_fp8x2_storage_t lo = __nv_cvt_float2_to_fp8x2(make_float2(v.x, v.y),
                                                       __NV_SATFINITE, __NV_E4M3);
    __nv_fp8x2_storage_t hi = __nv_cvt_float2_to_fp8x2(make_float2(v.z, v.w),
                                                       __NV_SATFINITE, __NV_E4M3);
    return (uint32_t)lo | ((uint32_t)hi << 16);
}

// ================= prep: f32 -> e4m3 =================
__global__ __launch_bounds__(512) void prep_x(const float* __restrict__ x) {
    size_t i = (size_t)blockIdx.x * 512 + threadIdx.x;     // over float4s
    reinterpret_cast<uint32_t*>(g_xq)[i] =
        pack_fp8x4(reinterpret_cast<const float4*>(x)[i]);
}
__global__ __launch_bounds__(512) void prep_cb(const float* __restrict__ cb) {
    size_t i = (size_t)blockIdx.x * 512 + threadIdx.x;
    reinterpret_cast<uint32_t*>(g_cbq)[i] =
        pack_fp8x4(reinterpret_cast<const float4*>(cb)[i]);
}

// ================= pass 0: ||c||^2 (fp64 accum) + reset flags =================
__global__ void c2_kernel(const float* __restrict__ cb) {
    if (blockIdx.x == 0 && threadIdx.x == 0) g_flag_count = 0;
    int cw   = blockIdx.x * (blockDim.x >> 5) + (threadIdx.x >> 5);
    int lane = threadIdx.x & 31;
    const float4* p = reinterpret_cast<const float4*>(cb + (size_t)cw * D);
    double s = 0.0;
    for (int t = lane; t < D / 4; t += 32) {
        float4 v = p[t];
        s += (double)v.x * v.x + (double)v.y * v.y + (double)v.z * v.z + (double)v.w * v.w;
    }
    #pragma unroll
    for (int o = 16; o; o >>= 1) s += __shfl_xor_sync(0xffffffffu, s, o);
    if (lane == 0) g_c2[cw] = (float)s;
}

// ================= pass A: e4m3 GEMM -> approx d2 matrix =================
__device__ __forceinline__ void stage_load(int s, int rowbase, uint32_t sbase, int tid) {
    const int ph = s >> 1;
    const int k0 = (s & 1) * KC;
    const uint32_t bufo = sbase + SM_BUF + (uint32_t)(s & 1) * BUF_BYTES;
    #pragma unroll
    for (int i = 0; i < 4; ++i) {                 // A: 128 rows x 16 chunks of 16B
        int id = tid + i * NTH;
        int row = id >> 4, kc = id & 15;
        CP16(bufo + row * STRIDE_B + kc * 16,
             g_xq + (size_t)(rowbase + row) * D + k0 + kc * 16);
    }
    #pragma unroll
    for (int i = 0; i < 8; ++i) {                 // B: 256 rows x 16 chunks of 16B
        int id = tid + i * NTH;
        int n = id >> 4, kc = id & 15;
        CP16(bufo + A_BYTES + n * STRIDE_B + kc * 16,
             g_cbq + (size_t)(ph * BN + n) * D + k0 + kc * 16);
    }
    CPCOMMIT();
}

__global__ __launch_bounds__(NTH, 1) void vq_gemm_kernel() {
    extern __shared__ char smem[];
    const uint32_t sbase = smem_u32(smem);
    const int tid   = threadIdx.x;
    const int lane  = tid & 31;
    const int wid   = tid >> 5;
    const int mwarp = wid >> 2;       // 0..3 -> 32 rows each
    const int nwarp = wid & 3;        // 0..3 -> 64 cols each
    const int rowbase = blockIdx.x * BM;

    float* s_c2 = reinterpret_cast<float*>(smem + SM_C2);
    for (int i = tid; i < KCB; i += NTH) s_c2[i] = g_c2[i];

    // ldmatrix offsets — 16-bit units hold 2 fp8; geometry identical to bf16 k16
    uint32_t aoff[2], boff[4];
    #pragma unroll
    for (int mt = 0; mt < 2; ++mt) {
        int row = mwarp * 32 + mt * 16 + (lane & 7) + ((lane >> 3) & 1) * 8;
        aoff[mt] = row * STRIDE_B + (lane >> 4) * 16;
    }
    #pragma unroll
    for (int p = 0; p < 4; ++p) {
        int n = nwarp * 64 + p * 16 + (lane & 7) + (lane >> 4) * 8;
        boff[p] = A_BYTES + n * STRIDE_B + ((lane >> 3) & 1) * 16;
    }

    float acc[2][8][4];

    stage_load(0, rowbase, sbase, tid);

    for (int s = 0; s < NSTG; ++s) {
        CPWAIT0();
        __syncthreads();
        if (s + 1 < NSTG) stage_load(s + 1, rowbase, sbase, tid);

        if ((s & 1) == 0) {
            #pragma unroll
            for (int mt = 0; mt < 2; ++mt)
                #pragma unroll
                for (int nt = 0; nt < 8; ++nt)
                    #pragma unroll
                    for (int r = 0; r < 4; ++r) acc[mt][nt][r] = 0.f;
        }

        const uint32_t bufo = sbase + SM_BUF + (uint32_t)(s & 1) * BUF_BYTES;
        #pragma unroll
        for (int ks = 0; ks < 8; ++ks) {          // 8 x k32 = KC=256
            uint32_t a0[4], a1[4];
            LDSM4(a0[0], a0[1], a0[2], a0[3], bufo + aoff[0] + ks * 32);
            LDSM4(a1[0], a1[1], a1[2], a1[3], bufo + aoff[1] + ks * 32);
            #pragma unroll
            for (int p = 0; p < 4; ++p) {
                uint32_t b0, b1, b2, b3;
                LDSM4(b0, b1, b2, b3, bufo + boff[p] + ks * 32);
                mma_fp8(acc[0][2 * p],     a0, b0, b1);
                mma_fp8(acc[0][2 * p + 1], a0, b2, b3);
                mma_fp8(acc[1][2 * p],     a1, b0, b1);
                mma_fp8(acc[1][2 * p + 1], a1, b2, b3);
            }
        }

        if ((s & 1) == 1) {
            const int ph = s >> 1;
            const int cbase = ph * BN + nwarp * 64 + (lane & 3) * 2;
            #pragma unroll
            for (int mt = 0; mt < 2; ++mt) {
                const int row0 = rowbase + mwarp * 32 + mt * 16 + (lane >> 2);
                #pragma unroll
                for (int nt = 0; nt < 8; ++nt) {
                    const int col0 = cbase + nt * 8;
                    const float c2a = s_c2[col0], c2b = s_c2[col0 + 1];
                    const float* a = acc[mt][nt];
                    float2 v0 = { fmaf(-2.f, a[0], c2a), fmaf(-2.f, a[1], c2b) };
                    float2 v1 = { fmaf(-2.f, a[2], c2a), fmaf(-2.f, a[3], c2b) };
                    *reinterpret_cast<float2*>(&g_d2[(size_t)row0 * KCB + col0]) = v0;
                    *reinterpret_cast<float2*>(&g_d2[(size_t)(row0 + 8) * KCB + col0]) = v1;
                }
            }
        }
    }
}

// ================= pass B: min + Kahan rescore + fused output =================
__global__ __launch_bounds__(256) void select_kernel(
    const float* __restrict__ x,
    const float* __restrict__ cb,
    float* __restrict__ out)
{
    __shared__ int s_cand[8][MAXCAND];
    __shared__ int s_cnt[8];

    const int wid  = threadIdx.x >> 5;
    const int lane = threadIdx.x & 31;
    const int row  = blockIdx.x * 8 + wid;

    const float* dr = g_d2 + (size_t)row * KCB;
    float vals[32];
    #pragma unroll
    for (int k = 0; k < 32; ++k) vals[k] = dr[lane + k * 32];

    // warp argmin (first-occurrence)
    float bv = vals[0]; int bi = lane;
    #pragma unroll
    for (int k = 1; k < 32; ++k) {
        int idx = lane + k * 32;
        if (vals[k] < bv || (vals[k] == bv && idx < bi)) { bv = vals[k]; bi = idx; }
    }
    #pragma unroll
    for (int o = 16; o; o >>= 1) {
        float ov = __shfl_xor_sync(0xffffffffu, bv, o);
        int   oi = __shfl_xor_sync(0xffffffffu, bi, o);
        if (ov < bv || (ov == bv && oi < bi)) { bv = ov; bi = oi; }
    }

    // collect candidates within margin
    if (lane == 0) s_cnt[wid] = 0;
    __syncwarp();
    const float thr = bv + MARGIN;
    #pragma unroll
    for (int k = 0; k < 32; ++k) {
        if (vals[k] < thr) {
            int slot = atomicAdd(&s_cnt[wid], 1);
            if (slot < MAXCAND) s_cand[wid][slot] = lane + k * 32;
        }
    }
    __syncwarp();
    const int cnt = s_cnt[wid];

    int winner = bi;
    if (cnt > MAXCAND) {                 // rare overflow -> full fp64 rescue
        if (lane == 0) {
            int slot = atomicAdd(&g_flag_count, 1);
            if (slot < CAP) g_flag_rows[slot] = row;
        }
        return;                          // rescue writes the output row
    }

    if (cnt > 1) {
        // Kahan-fp32 rescore of candidates
        float xf[16];
        #pragma unroll
        for (int j = 0; j < 16; ++j) xf[j] = x[(size_t)row * D + lane + j * 32];

        float x2s = 0.f, x2c = 0.f;
        #pragma unroll
        for (int j = 0; j < 16; ++j) {
            float p = xf[j] * xf[j];
            float y = p - x2c; float t = x2s + y; x2c = (t - x2s) - y; x2s = t;
        }
        #pragma unroll
        for (int o = 16; o; o >>= 1) x2s += __shfl_xor_sync(0xffffffffu, x2s, o);

        float b1v = FLT_MAX, b2v = FLT_MAX; int b1i = 1 << 30, b2i = 1 << 30;
        for (int t0 = 0; t0 < cnt; ++t0) {
            const int c = s_cand[wid][t0];
            const float* cr = cb + (size_t)c * D;
            float ds = 0.f, dc = 0.f;
            #pragma unroll
            for (int j = 0; j < 16; ++j) {
                float p = xf[j] * cr[lane + j * 32];
                float y = p - dc; float t = ds + y; dc = (t - ds) - y; ds = t;
            }
            #pragma unroll
            for (int o = 16; o; o >>= 1) ds += __shfl_xor_sync(0xffffffffu, ds, o);
            float d2 = (x2s - 2.0f * ds) + g_c2[c];
            if (d2 < b1v || (d2 == b1v && c < b1i)) { b2v = b1v; b2i = b1i; b1v = d2; b1i = c; }
            else if (d2 < b2v) { b2v = d2; b2i = c; }
        }
        winner = b1i;

        if (b2v - b1v < TIEBREAK) {      // too close for Kahan: fp64 on fp32 grid
            double x2d = 0.0;
            #pragma unroll
            for (int j = 0; j < 16; ++j) x2d += (double)xf[j] * xf[j];
            #pragma unroll
            for (int o = 16; o; o >>= 1) x2d += __shfl_xor_sync(0xffffffffu, x2d, o);
            const float x2f = (float)x2d;
            float dv[2]; int ci[2] = { b1i, b2i };
            #pragma unroll
            for (int t1 = 0; t1 < 2; ++t1) {
                const float* cr = cb + (size_t)ci[t1] * D;
                double dot = 0.0;
                #pragma unroll
                for (int j = 0; j < 16; ++j)
                    dot += (double)xf[j] * (double)cr[lane + j * 32];
                #pragma unroll
                for (int o = 16; o; o >>= 1) dot += __shfl_xor_sync(0xffffffffu, dot, o);
                dv[t1] = (x2f - 2.0f * (float)dot) + g_c2[ci[t1]];
            }
            if (dv[1] < dv[0] || (dv[1] == dv[0] && ci[1] < ci[0])) winner = ci[1];
            else winner = ci[0];
        }
    }

    // fused gather: write winning codeword
    const float4* src = reinterpret_cast<const float4*>(cb + (size_t)winner * D);
    float4* dst = reinterpret_cast<float4*>(out + (size_t)row * D);
    #pragma unroll
    for (int j = 0; j < 4; ++j)
        dst[lane + j * 32] = src[lane + j * 32];
}

// ================= rescue: full fp64 rescore + output (overflow rows) =================
__global__ __launch_bounds__(256) void rescue_kernel(
    const float* __restrict__ x,
    const float* __restrict__ cb,
    float* __restrict__ out)
{
    __shared__ float sx[D];
    __shared__ float wv[8];
    __shared__ int   wi[8];
    __shared__ int   s_win;

    const int tid  = threadIdx.x;
    const int wid  = tid >> 5;
    const int lane = tid & 31;
    int total = g_flag_count;
    if (total > CAP) total = CAP;

    for (int f = blockIdx.x; f < total; f += gridDim.x) {
        const int row = g_flag_rows[f];
        for (int i = tid; i < D; i += 256) sx[i] = x[(size_t)row * D + i];
        __syncthreads();

        double x2 = 0.0;
        for (int e = lane; e < D; e += 32) { double v = (double)sx[e]; x2 += v * v; }
        #pragma unroll
        for (int o = 16; o; o >>= 1) x2 += __shfl_xor_sync(0xffffffffu, x2, o);
        const float x2f = (float)x2;

        float bv = FLT_MAX;
        int   bi = 1 << 30;
        for (int cw = wid; cw < KCB; cw += 8) {
            const float* c = cb + (size_t)cw * D;
            double dot = 0.0;
            for (int e = lane; e < D; e += 32)
                dot += (double)sx[e] * (double)c[e];
            #pragma unroll
            for (int o = 16; o; o >>= 1) dot += __shfl_xor_sync(0xffffffffu, dot, o);
            float d2 = (x2f - 2.0f * (float)dot) + g_c2[cw];
            if (d2 < bv) { bv = d2; bi = cw; }
        }
        if (lane == 0) { wv[wid] = bv; wi[wid] = bi; }
        __syncthreads();
        if (tid == 0) {
            float fbv = wv[0]; int fbi = wi[0];
            #pragma unroll
            for (int t = 1; t < 8; ++t)
                if (wv[t] < fbv || (wv[t] == fbv && wi[t] < fbi)) { fbv = wv[t]; fbi = wi[t]; }
            s_win = fbi;
        }
        __syncthreads();
        const int w = s_win;
        if (tid < 128) {
            reinterpret_cast<float4*>(out + (size_t)row * D)[tid] =
                reinterpret_cast<const float4*>(cb + (size_t)w * D)[tid];
        }
        __syncthreads();
    }
}

extern "C" void kernel_launch(void* const* d_in, const int* in_sizes, int n_in,
                              void* d_out, int out_size) {
    const float* x  = (const float*)d_in[0];   // [65536, 512]
    const float* cb = (const float*)d_in[1];   // [1024, 512]
    float* out = (float*)d_out;
    int nrows = in_sizes[0] / D;               // 65536

    cudaFuncSetAttribute(vq_gemm_kernel,
                         cudaFuncAttributeMaxDynamicSharedMemorySize, SM_TOTAL);

    prep_x<<<(int)((size_t)nrows * D / 4 / 512), 512>>>(x);
    prep_cb<<<KCB * D / 4 / 512, 512>>>(cb);
    c2_kernel<<<KCB / 8, 256>>>(cb);
    vq_gemm_kernel<<<nrows / BM, NTH, SM_TOTAL>>>();
    select_kernel<<<nrows / 8, 256>>>(x, cb, out);
    rescue_kernel<<<296, 256>>>(x, cb, out);
}

// round 15
// speedup vs baseline: 2.4710x; 2.4710x over previous
#include <cuda_runtime.h>
#include <cuda_bf16.h>
#include <cfloat>
#include <cstdint>

#define D        512
#define KCB      1024
#define NROWS    65536
#define MARGIN   1.5f
#define CAP      65536
#define MAXCAND  12

#define BM       128            // rows per CTA
#define BN       128            // codewords per phase
#define NPH      8              // 1024 / 128
#define KC       64             // K elems per stage
#define KSTG     (D / KC)       // 8 k-stages per phase
#define NSTG     (NPH * KSTG)   // 64
#define NTH      256

// smem layout (bytes) — 76 KB/CTA -> 2 CTAs per SM
#define SM_C2    0               // float[1024]
#define SM_BUF   4096
#define STRIDE_B 144             // 128B data + 16B pad -> conflict-free ldmatrix (R5-proven)
#define A_BYTES  (BM * STRIDE_B)          // 18432
#define B_BYTES  (BN * STRIDE_B)          // 18432
#define BUF_BYTES (A_BYTES + B_BYTES)     // 36864
#define SM_TOTAL (SM_BUF + 2 * BUF_BYTES) // 77824

// ---- device scratch (no cudaMalloc allowed) ----
__device__ __nv_bfloat16 g_xhi[(size_t)NROWS * D];   // 64 MB
__device__ __nv_bfloat16 g_cbhi[KCB * D];            // 1 MB
__device__ float g_d2[(size_t)NROWS * KCB];          // 256 MB approx distances
__device__ float g_c2[KCB];
__device__ int   g_flag_rows[CAP];
__device__ int   g_flag_count;

// ================= PTX helpers (baseline sm_80 features only) =================
__device__ __forceinline__ uint32_t smem_u32(const void* p) {
    uint32_t a;
    asm("{ .reg .u64 t; cvta.to.shared.u64 t, %1; cvt.u32.u64 %0, t; }" : "=r"(a) : "l"(p));
    return a;
}
#define CP16(s, g)   asm volatile("cp.async.ca.shared.global [%0], [%1], 16;" :: "r"(s), "l"(g))
#define CPCOMMIT()   asm volatile("cp.async.commit_group;")
#define CPWAIT0()    asm volatile("cp.async.wait_group 0;")
#define LDSM4(r0, r1, r2, r3, a) \
    asm volatile("ldmatrix.sync.aligned.m8n8.x4.shared.b16 {%0,%1,%2,%3}, [%4];" \
                 : "=r"(r0), "=r"(r1), "=r"(r2), "=r"(r3) : "r"(a))

__device__ __forceinline__ void mma_bf16(float* c, const uint32_t* a, uint32_t b0, uint32_t b1) {
    asm volatile(
        "mma.sync.aligned.m16n8k16.row.col.f32.bf16.bf16.f32 "
        "{%0,%1,%2,%3}, {%4,%5,%6,%7}, {%8,%9}, {%0,%1,%2,%3};"
        : "+f"(c[0]), "+f"(c[1]), "+f"(c[2]), "+f"(c[3])
        : "r"(a[0]), "r"(a[1]), "r"(a[2]), "r"(a[3]), "r"(b0), "r"(b1));
}

// ================= prep: f32 -> bf16 hi =================
__global__ __launch_bounds__(512) void prep_x(const float* __restrict__ x) {
    size_t i = (size_t)blockIdx.x * 512 + threadIdx.x;     // over float4s
    float4 v = reinterpret_cast<const float4*>(x)[i];
    __nv_bfloat162 h01 = __floats2bfloat162_rn(v.x, v.y);
    __nv_bfloat162 h23 = __floats2bfloat162_rn(v.z, v.w);
    uint2 hw;
    hw.x = *reinterpret_cast<uint32_t*>(&h01); hw.y = *reinterpret_cast<uint32_t*>(&h23);
    reinterpret_cast<uint2*>(g_xhi)[i] = hw;
}
__global__ __launch_bounds__(512) void prep_cb(const float* __restrict__ cb) {
    size_t i = (size_t)blockIdx.x * 512 + threadIdx.x;
    float4 v = reinterpret_cast<const float4*>(cb)[i];
    __nv_bfloat162 h01 = __floats2bfloat162_rn(v.x, v.y);
    __nv_bfloat162 h23 = __floats2bfloat162_rn(v.z, v.w);
    uint2 hw;
    hw.x = *reinterpret_cast<uint32_t*>(&h01); hw.y = *reinterpret_cast<uint32_t*>(&h23);
    reinterpret_cast<uint2*>(g_cbhi)[i] = hw;
}

// ================= pass 0: ||c||^2 (fp64 accum) + reset flags =================
__global__ void c2_kernel(const float* __restrict__ cb) {
    if (blockIdx.x == 0 && threadIdx.x == 0) g_flag_count = 0;
    int cw   = blockIdx.x * (blockDim.x >> 5) + (threadIdx.x >> 5);
    int lane = threadIdx.x & 31;
    const float4* p = reinterpret_cast<const float4*>(cb + (size_t)cw * D);
    double s = 0.0;
    for (int t = lane; t < D / 4; t += 32) {
        float4 v = p[t];
        s += (double)v.x * v.x + (double)v.y * v.y + (double)v.z * v.z + (double)v.w * v.w;
    }
    #pragma unroll
    for (int o = 16; o; o >>= 1) s += __shfl_xor_sync(0xffffffffu, s, o);
    if (lane == 0) g_c2[cw] = (float)s;
}

// ================= pass A: hi*hi GEMM -> approx d2 matrix =================
__device__ __forceinline__ void stage_load(int s, int rowbase, uint32_t sbase, int tid) {
    const int ph = s >> 3;                 // phase: 128-col block
    const int k0 = (s & 7) * KC;
    const uint32_t bufo = sbase + SM_BUF + (uint32_t)(s & 1) * BUF_BYTES;
    #pragma unroll
    for (int i = 0; i < 4; ++i) {                 // A: 128 rows x 8 chunks of 16B
        int id = tid + i * NTH;
        int row = id >> 3, kc = id & 7;
        CP16(bufo + row * STRIDE_B + kc * 16,
             g_xhi + (size_t)(rowbase + row) * D + k0 + kc * 8);
    }
    #pragma unroll
    for (int i = 0; i < 4; ++i) {                 // B: 128 rows x 8 chunks of 16B
        int id = tid + i * NTH;
        int n = id >> 3, kc = id & 7;
        CP16(bufo + A_BYTES + n * STRIDE_B + kc * 16,
             g_cbhi + (size_t)(ph * BN + n) * D + k0 + kc * 8);
    }
    CPCOMMIT();
}

__global__ __launch_bounds__(NTH, 2) void vq_gemm_kernel() {
    extern __shared__ char smem[];
    const uint32_t sbase = smem_u32(smem);
    const int tid   = threadIdx.x;
    const int lane  = tid & 31;
    const int wid   = tid >> 5;
    const int mwarp = wid >> 1;       // 0..3 -> 32 rows each
    const int nwarp = wid & 1;        // 0..1 -> 64 cols each
    const int rowbase = blockIdx.x * BM;

    float* s_c2 = reinterpret_cast<float*>(smem + SM_C2);
    for (int i = tid; i < KCB; i += NTH) s_c2[i] = g_c2[i];

    // per-thread ldmatrix offsets (within buffer)
    uint32_t aoff[2], boff[4];
    #pragma unroll
    for (int mt = 0; mt < 2; ++mt) {
        int row = mwarp * 32 + mt * 16 + (lane & 7) + ((lane >> 3) & 1) * 8;
        aoff[mt] = row * STRIDE_B + (lane >> 4) * 16;
    }
    #pragma unroll
    for (int p = 0; p < 4; ++p) {
        int n = nwarp * 64 + p * 16 + (lane & 7) + (lane >> 4) * 8;
        boff[p] = A_BYTES + n * STRIDE_B + ((lane >> 3) & 1) * 16;
    }

    float acc[2][8][4];

    stage_load(0, rowbase, sbase, tid);

    for (int s = 0; s < NSTG; ++s) {
        CPWAIT0();            // buf[s&1] fully staged
        __syncthreads();      // all warps done with compute(s-1)
        if (s + 1 < NSTG) stage_load(s + 1, rowbase, sbase, tid);

        if ((s & 7) == 0) {
            #pragma unroll
            for (int mt = 0; mt < 2; ++mt)
                #pragma unroll
                for (int nt = 0; nt < 8; ++nt)
                    #pragma unroll
                    for (int r = 0; r < 4; ++r) acc[mt][nt][r] = 0.f;
        }

        const uint32_t bufo = sbase + SM_BUF + (uint32_t)(s & 1) * BUF_BYTES;
        #pragma unroll
        for (int ks = 0; ks < 4; ++ks) {          // KC=64 -> 4 x k16
            uint32_t a0[4], a1[4];
            LDSM4(a0[0], a0[1], a0[2], a0[3], bufo + aoff[0] + ks * 32);
            LDSM4(a1[0], a1[1], a1[2], a1[3], bufo + aoff[1] + ks * 32);
            #pragma unroll
            for (int p = 0; p < 4; ++p) {
                uint32_t b0, b1, b2, b3;
                LDSM4(b0, b1, b2, b3, bufo + boff[p] + ks * 32);
                mma_bf16(acc[0][2 * p],     a0, b0, b1);
                mma_bf16(acc[0][2 * p + 1], a0, b2, b3);
                mma_bf16(acc[1][2 * p],     a1, b0, b1);
                mma_bf16(acc[1][2 * p + 1], a1, b2, b3);
            }
        }

        if ((s & 7) == 7) {
            const int ph = s >> 3;
            const int cbase = ph * BN + nwarp * 64 + (lane & 3) * 2;
            #pragma unroll
            for (int mt = 0; mt < 2; ++mt) {
                const int row0 = rowbase + mwarp * 32 + mt * 16 + (lane >> 2);
                #pragma unroll
                for (int nt = 0; nt < 8; ++nt) {
                    const int col0 = cbase + nt * 8;
                    const float c2a = s_c2[col0], c2b = s_c2[col0 + 1];
                    const float* a = acc[mt][nt];
                    float2 v0 = { fmaf(-2.f, a[0], c2a), fmaf(-2.f, a[1], c2b) };
                    float2 v1 = { fmaf(-2.f, a[2], c2a), fmaf(-2.f, a[3], c2b) };
                    *reinterpret_cast<float2*>(&g_d2[(size_t)row0 * KCB + col0]) = v0;
                    *reinterpret_cast<float2*>(&g_d2[(size_t)(row0 + 8) * KCB + col0]) = v1;
                }
            }
        }
    }
}

// ================= pass B: min + candidate rescore + fused output =================
__global__ __launch_bounds__(256) void select_kernel(
    const float* __restrict__ x,
    const float* __restrict__ cb,
    float* __restrict__ out)
{
    __shared__ int s_cand[8][MAXCAND];
    __shared__ int s_cnt[8];

    const int wid  = threadIdx.x >> 5;
    const int lane = threadIdx.x & 31;
    const int row  = blockIdx.x * 8 + wid;

    const float* dr = g_d2 + (size_t)row * KCB;
    float vals[32];
    #pragma unroll
    for (int k = 0; k < 32; ++k) vals[k] = dr[lane + k * 32];

    // warp argmin (first-occurrence: tie -> lower index)
    float bv = vals[0]; int bi = lane;
    #pragma unroll
    for (int k = 1; k < 32; ++k) {
        int idx = lane + k * 32;
        if (vals[k] < bv || (vals[k] == bv && idx < bi)) { bv = vals[k]; bi = idx; }
    }
    #pragma unroll
    for (int o = 16; o; o >>= 1) {
        float ov = __shfl_xor_sync(0xffffffffu, bv, o);
        int   oi = __shfl_xor_sync(0xffffffffu, bi, o);
        if (ov < bv || (ov == bv && oi < bi)) { bv = ov; bi = oi; }
    }

    // collect candidates within margin
    if (lane == 0) s_cnt[wid] = 0;
    __syncwarp();
    const float thr = bv + MARGIN;
    #pragma unroll
    for (int k = 0; k < 32; ++k) {
        if (vals[k] < thr) {
            int slot = atomicAdd(&s_cnt[wid], 1);
            if (slot < MAXCAND) s_cand[wid][slot] = lane + k * 32;
        }
    }
    __syncwarp();
    const int cnt = s_cnt[wid];

    int winner = bi;
    if (cnt > MAXCAND) {                 // rare overflow -> full fp64 rescue
        if (lane == 0) {
            int slot = atomicAdd(&g_flag_count, 1);
            if (slot < CAP) g_flag_rows[slot] = row;
        }
        return;                          // rescue writes the output row
    }

    if (cnt > 1) {
        // exact rescore on the reference fp32 grid (fp64 dots) — R9-proven
        float xf[16];
        #pragma unroll
        for (int j = 0; j < 16; ++j) xf[j] = x[(size_t)row * D + lane + j * 32];
        double x2 = 0.0;
        #pragma unroll
        for (int j = 0; j < 16; ++j) x2 += (double)xf[j] * xf[j];
        #pragma unroll
        for (int o = 16; o; o >>= 1) x2 += __shfl_xor_sync(0xffffffffu, x2, o);
        const float x2f = (float)x2;

        float bvf = FLT_MAX; int bci = 1 << 30;
        for (int t = 0; t < cnt; ++t) {
            const int c = s_cand[wid][t];
            const float* cr = cb + (size_t)c * D;
            double dot = 0.0;
            #pragma unroll
            for (int j = 0; j < 16; ++j)
                dot += (double)xf[j] * (double)cr[lane + j * 32];
            #pragma unroll
            for (int o = 16; o; o >>= 1) dot += __shfl_xor_sync(0xffffffffu, dot, o);
            float d2 = (x2f - 2.0f * (float)dot) + g_c2[c];
            if (d2 < bvf || (d2 == bvf && c < bci)) { bvf = d2; bci = c; }
        }
        winner = bci;
    }

    // fused gather: write winning codeword row
    const float4* src = reinterpret_cast<const float4*>(cb + (size_t)winner * D);
    float4* dst = reinterpret_cast<float4*>(out + (size_t)row * D);
    #pragma unroll
    for (int j = 0; j < 4; ++j)
        dst[lane + j * 32] = src[lane + j * 32];
}

// ================= rescue: full fp64 rescore + output (overflow rows) =================
__global__ __launch_bounds__(256) void rescue_kernel(
    const float* __restrict__ x,
    const float* __restrict__ cb,
    float* __restrict__ out)
{
    __shared__ float sx[D];
    __shared__ float wv[8];
    __shared__ int   wi[8];
    __shared__ int   s_win;

    const int tid  = threadIdx.x;
    const int wid  = tid >> 5;
    const int lane = tid & 31;
    int total = g_flag_count;
    if (total > CAP) total = CAP;

    for (int f = blockIdx.x; f < total; f += gridDim.x) {
        const int row = g_flag_rows[f];
        for (int i = tid; i < D; i += 256) sx[i] = x[(size_t)row * D + i];
        __syncthreads();

        double x2 = 0.0;
        for (int e = lane; e < D; e += 32) { double v = (double)sx[e]; x2 += v * v; }
        #pragma unroll
        for (int o = 16; o; o >>= 1) x2 += __shfl_xor_sync(0xffffffffu, x2, o);
        const float x2f = (float)x2;

        float bv = FLT_MAX;
        int   bi = 1 << 30;
        for (int cw = wid; cw < KCB; cw += 8) {
            const float* c = cb + (size_t)cw * D;
            double dot = 0.0;
            for (int e = lane; e < D; e += 32)
                dot += (double)sx[e] * (double)c[e];
            #pragma unroll
            for (int o = 16; o; o >>= 1) dot += __shfl_xor_sync(0xffffffffu, dot, o);
            float d2 = (x2f - 2.0f * (float)dot) + g_c2[cw];
            if (d2 < bv) { bv = d2; bi = cw; }
        }
        if (lane == 0) { wv[wid] = bv; wi[wid] = bi; }
        __syncthreads();
        if (tid == 0) {
            float fbv = wv[0]; int fbi = wi[0];
            #pragma unroll
            for (int t = 1; t < 8; ++t)
                if (wv[t] < fbv || (wv[t] == fbv && wi[t] < fbi)) { fbv = wv[t]; fbi = wi[t]; }
            s_win = fbi;
        }
        __syncthreads();
        const int w = s_win;
        if (tid < 128) {
            reinterpret_cast<float4*>(out + (size_t)row * D)[tid] =
                reinterpret_cast<const float4*>(cb + (size_t)w * D)[tid];
        }
        __syncthreads();
    }
}

extern "C" void kernel_launch(void* const* d_in, const int* in_sizes, int n_in,
                              void* d_out, int out_size) {
    const float* x  = (const float*)d_in[0];   // [65536, 512]
    const float* cb = (const float*)d_in[1];   // [1024, 512]
    float* out = (float*)d_out;
    int nrows = in_sizes[0] / D;               // 65536

    cudaFuncSetAttribute(vq_gemm_kernel,
                         cudaFuncAttributeMaxDynamicSharedMemorySize, SM_TOTAL);

    prep_x<<<(int)((size_t)nrows * D / 4 / 512), 512>>>(x);
    prep_cb<<<KCB * D / 4 / 512, 512>>>(cb);
    c2_kernel<<<KCB / 8, 256>>>(cb);
    vq_gemm_kernel<<<nrows / BM, NTH, SM_TOTAL>>>();
    select_kernel<<<nrows / 8, 256>>>(x, cb, out);
    rescue_kernel<<<296, 256>>>(x, cb, out);
}